// round 3
// baseline (speedup 1.0000x reference)
#include <cuda_runtime.h>
#include <cuda_bf16.h>

// Problem constants
#define BQ 8
#define TQ 1024
#define CQ 768
#define HQ 8
#define DQ 96
#define C3 2304          // 3*C
#define MROWS (BQ*TQ)    // 8192

// Scratch (device globals; no cudaMalloc allowed)
__device__ float g_qkv[MROWS * C3];   // (B*T, 3C) qkv projection output
__device__ float g_att[MROWS * CQ];   // (B, T, H, D) attention output, contiguous (B*T, C)

// ---------------------------------------------------------------------------
// Packed fp32x2 helpers (sm_103a: fma.rn.f32x2 doubles fp32 FMA throughput)
// ---------------------------------------------------------------------------
__device__ __forceinline__ unsigned long long pack2(float x, float y) {
    unsigned long long r;
    asm("mov.b64 %0, {%1, %2};" : "=l"(r) : "f"(x), "f"(y));
    return r;
}
__device__ __forceinline__ void fma2(unsigned long long& d,
                                     unsigned long long a,
                                     unsigned long long b) {
    asm("fma.rn.f32x2 %0, %1, %2, %0;" : "+l"(d) : "l"(a), "l"(b));
}

// ---------------------------------------------------------------------------
// NT GEMM: C[m,n] = sum_k A[m,k] * B[n,k] + bias[n]
// A: (M,K) row-major, B: (N,K) row-major, C: (M,N) row-major
// BM=BN=128, BK=16, 256 threads, 8x8 microtile via fp32x2 pairs.
// Requires M%128==0, N%128==0, K%16==0 (true for all our shapes).
// ---------------------------------------------------------------------------
#define GBM 128
#define GBN 128
#define GBK 16

__global__ void __launch_bounds__(256)
gemm_nt_kernel(const float* __restrict__ A, const float* __restrict__ B,
               const float* __restrict__ bias, float* __restrict__ C,
               int M, int N, int K)
{
    __shared__ float As[GBK][GBM];
    __shared__ float Bs[GBK][GBN];

    const int tid = threadIdx.x;
    const int bm0 = blockIdx.y * GBM;
    const int bn0 = blockIdx.x * GBN;
    const int tx = tid & 15;     // 0..15 -> column octet
    const int ty = tid >> 4;     // 0..15 -> row octet

    unsigned long long acc[8][4];
#pragma unroll
    for (int i = 0; i < 8; i++)
#pragma unroll
        for (int j = 0; j < 4; j++) acc[i][j] = 0ull;

    for (int k0 = 0; k0 < K; k0 += GBK) {
        // Load A tile (128x16) and B tile (128x16), store transposed [k][row]
#pragma unroll
        for (int t = 0; t < 2; t++) {
            int i = tid + t * 256;           // 0..511 float4 slots
            int r = i >> 2, cg = (i & 3) * 4;
            float4 va = *(const float4*)&A[(long long)(bm0 + r) * K + k0 + cg];
            As[cg + 0][r] = va.x; As[cg + 1][r] = va.y;
            As[cg + 2][r] = va.z; As[cg + 3][r] = va.w;
            float4 vb = *(const float4*)&B[(long long)(bn0 + r) * K + k0 + cg];
            Bs[cg + 0][r] = vb.x; Bs[cg + 1][r] = vb.y;
            Bs[cg + 2][r] = vb.z; Bs[cg + 3][r] = vb.w;
        }
        __syncthreads();

#pragma unroll
        for (int kk = 0; kk < GBK; kk++) {
            float4 a0 = *(const float4*)&As[kk][ty * 8];
            float4 a1 = *(const float4*)&As[kk][ty * 8 + 4];
            float4 b0 = *(const float4*)&Bs[kk][tx * 8];
            float4 b1 = *(const float4*)&Bs[kk][tx * 8 + 4];
            unsigned long long bp[4];
            bp[0] = pack2(b0.x, b0.y); bp[1] = pack2(b0.z, b0.w);
            bp[2] = pack2(b1.x, b1.y); bp[3] = pack2(b1.z, b1.w);
            float ar[8] = {a0.x, a0.y, a0.z, a0.w, a1.x, a1.y, a1.z, a1.w};
#pragma unroll
            for (int i = 0; i < 8; i++) {
                unsigned long long av = pack2(ar[i], ar[i]);
                fma2(acc[i][0], av, bp[0]);
                fma2(acc[i][1], av, bp[1]);
                fma2(acc[i][2], av, bp[2]);
                fma2(acc[i][3], av, bp[3]);
            }
        }
        __syncthreads();
    }

    // Epilogue: add bias, write out
    float4 bi0 = *(const float4*)&bias[bn0 + tx * 8];
    float4 bi1 = *(const float4*)&bias[bn0 + tx * 8 + 4];
#pragma unroll
    for (int i = 0; i < 8; i++) {
        float2 c0 = *(float2*)&acc[i][0];
        float2 c1 = *(float2*)&acc[i][1];
        float2 c2 = *(float2*)&acc[i][2];
        float2 c3 = *(float2*)&acc[i][3];
        float4 o0 = make_float4(c0.x + bi0.x, c0.y + bi0.y, c1.x + bi0.z, c1.y + bi0.w);
        float4 o1 = make_float4(c2.x + bi1.x, c2.y + bi1.y, c3.x + bi1.z, c3.y + bi1.w);
        long long row = bm0 + ty * 8 + i;
        *(float4*)&C[row * N + bn0 + tx * 8]     = o0;
        *(float4*)&C[row * N + bn0 + tx * 8 + 4] = o1;
    }
}

// ---------------------------------------------------------------------------
// Flash attention (causal), fp32.
// Grid: (T/64, B*H). 256 threads = 8 warps; warp w owns 8 query rows.
// Q/K/V tiles of 64 rows x 96 dims in smem (row stride 100 -> conflict-free),
// P (softmax weights) staged through smem for broadcast PV reads.
// ---------------------------------------------------------------------------
#define ASTR 100
#define ATT_SMEM ((3 * 64 * ASTR + 64 * 64) * sizeof(float))   // 93184 bytes

__global__ void __launch_bounds__(256)
attn_kernel()
{
    extern __shared__ float sm[];
    float* Qs = sm;                 // 64 x 100
    float* Ks = sm + 64 * ASTR;     // 64 x 100
    float* Vs = sm + 2 * 64 * ASTR; // 64 x 100
    float* Ps = sm + 3 * 64 * ASTR; // 64 x 64

    const int tid = threadIdx.x;
    const int lane = tid & 31;
    const int w = tid >> 5;
    const int qt = blockIdx.x;
    const int bh = blockIdx.y;
    const int b = bh >> 3, h = bh & 7;
    const int q0 = qt * 64;

    const float* base = g_qkv + (long long)b * TQ * C3 + h * DQ;

    // Load Q tile: 64 rows x 96 floats = 1536 float4
    for (int i = tid; i < 64 * 24; i += 256) {
        int r = i / 24, cg = (i % 24) * 4;
        *(float4*)&Qs[r * ASTR + cg] =
            *(const float4*)&base[(long long)(q0 + r) * C3 + cg];
    }

    float m_i[8], l_i[8], acc[8][3];
#pragma unroll
    for (int qr = 0; qr < 8; qr++) {
        m_i[qr] = -1e30f; l_i[qr] = 0.f;
        acc[qr][0] = acc[qr][1] = acc[qr][2] = 0.f;
    }

    const float scale = 0.1020620726159658f; // 1/sqrt(96)

    for (int j = 0; j <= qt; j++) {
        __syncthreads();
        const int k0r = j * 64;
        for (int i = tid; i < 64 * 24; i += 256) {
            int r = i / 24, cg = (i % 24) * 4;
            long long src = (long long)(k0r + r) * C3 + cg;
            *(float4*)&Ks[r * ASTR + cg] = *(const float4*)&base[src + 768];
            *(float4*)&Vs[r * ASTR + cg] = *(const float4*)&base[src + 1536];
        }
        __syncthreads();

        // --- scores: lane owns keys (lane, lane+32) ---
        float s[8][2];
#pragma unroll
        for (int qr = 0; qr < 8; qr++) { s[qr][0] = 0.f; s[qr][1] = 0.f; }

#pragma unroll 6
        for (int c = 0; c < 24; c++) {
            float4 ka = *(const float4*)&Ks[lane * ASTR + c * 4];
            float4 kb = *(const float4*)&Ks[(lane + 32) * ASTR + c * 4];
#pragma unroll
            for (int qr = 0; qr < 8; qr++) {
                float4 qv = *(const float4*)&Qs[(w * 8 + qr) * ASTR + c * 4];
                s[qr][0] += qv.x * ka.x + qv.y * ka.y + qv.z * ka.z + qv.w * ka.w;
                s[qr][1] += qv.x * kb.x + qv.y * kb.y + qv.z * kb.z + qv.w * kb.w;
            }
        }

        // --- online softmax per row ---
        const bool diag = (j == qt);
#pragma unroll
        for (int qr = 0; qr < 8; qr++) {
            const int qg = q0 + w * 8 + qr;
            float s0 = s[qr][0] * scale;
            float s1 = s[qr][1] * scale;
            if (diag) {
                if (k0r + lane      > qg) s0 = -1e30f;
                if (k0r + lane + 32 > qg) s1 = -1e30f;
            }
            float mx = fmaxf(s0, s1);
#pragma unroll
            for (int o = 16; o; o >>= 1)
                mx = fmaxf(mx, __shfl_xor_sync(0xffffffffu, mx, o));
            float m_new = fmaxf(m_i[qr], mx);
            float p0 = __expf(s0 - m_new);
            float p1 = __expf(s1 - m_new);
            float rs = p0 + p1;
#pragma unroll
            for (int o = 16; o; o >>= 1)
                rs += __shfl_xor_sync(0xffffffffu, rs, o);
            float alpha = __expf(m_i[qr] - m_new);
            l_i[qr] = l_i[qr] * alpha + rs;
            m_i[qr] = m_new;
            acc[qr][0] *= alpha; acc[qr][1] *= alpha; acc[qr][2] *= alpha;
            Ps[(w * 8 + qr) * 64 + lane]      = p0;
            Ps[(w * 8 + qr) * 64 + lane + 32] = p1;
        }
        __syncwarp();

        // --- PV: lane owns dims (lane, lane+32, lane+64) ---
#pragma unroll 4
        for (int k4 = 0; k4 < 16; k4++) {
            float v[4][3];
#pragma unroll
            for (int u = 0; u < 4; u++) {
                int key = k4 * 4 + u;
                v[u][0] = Vs[key * ASTR + lane];
                v[u][1] = Vs[key * ASTR + lane + 32];
                v[u][2] = Vs[key * ASTR + lane + 64];
            }
#pragma unroll
            for (int qr = 0; qr < 8; qr++) {
                float4 p = *(const float4*)&Ps[(w * 8 + qr) * 64 + k4 * 4];
                acc[qr][0] += p.x * v[0][0] + p.y * v[1][0] + p.z * v[2][0] + p.w * v[3][0];
                acc[qr][1] += p.x * v[0][1] + p.y * v[1][1] + p.z * v[2][1] + p.w * v[3][1];
                acc[qr][2] += p.x * v[0][2] + p.y * v[1][2] + p.z * v[2][2] + p.w * v[3][2];
            }
        }
    }

    // Normalize + write (B,T,H,D) contiguous
#pragma unroll
    for (int qr = 0; qr < 8; qr++) {
        float inv = 1.0f / l_i[qr];
        int t = q0 + w * 8 + qr;
        float* o = g_att + ((long long)(b * TQ + t)) * CQ + h * DQ;
        o[lane]      = acc[qr][0] * inv;
        o[lane + 32] = acc[qr][1] * inv;
        o[lane + 64] = acc[qr][2] * inv;
    }
}

// ---------------------------------------------------------------------------
// Launch
// ---------------------------------------------------------------------------
extern "C" void kernel_launch(void* const* d_in, const int* in_sizes, int n_in,
                              void* d_out, int out_size)
{
    const float* x      = (const float*)d_in[0];
    const float* w_attn = (const float*)d_in[1];
    const float* b_attn = (const float*)d_in[2];
    const float* w_proj = (const float*)d_in[3];
    const float* b_proj = (const float*)d_in[4];
    float* out = (float*)d_out;

    float* qkv; cudaGetSymbolAddress((void**)&qkv, g_qkv);
    float* att; cudaGetSymbolAddress((void**)&att, g_att);

    // 1) QKV projection: (8192 x 768) @ (2304 x 768)^T
    gemm_nt_kernel<<<dim3(C3 / GBN, MROWS / GBM), 256>>>(
        x, w_attn, b_attn, qkv, MROWS, C3, CQ);

    // 2) Causal flash attention
    cudaFuncSetAttribute(attn_kernel,
                         cudaFuncAttributeMaxDynamicSharedMemorySize,
                         (int)ATT_SMEM);
    attn_kernel<<<dim3(TQ / 64, BQ * HQ), 256, ATT_SMEM>>>();

    // 3) Output projection: (8192 x 768) @ (768 x 768)^T
    gemm_nt_kernel<<<dim3(CQ / GBN, MROWS / GBM), 256>>>(
        att, w_proj, b_proj, out, MROWS, CQ, CQ);
}

// round 10
// speedup vs baseline: 1.5819x; 1.5819x over previous
#include <cuda_runtime.h>
#include <cuda_bf16.h>
#include <cstdint>

// Problem constants
#define BQ 8
#define TQ 1024
#define CQ 768
#define HQ 8
#define DQ 96
#define C3 2304          // 3*C
#define MROWS (BQ*TQ)    // 8192
#define GK 768           // K dim for both GEMMs
#define NCH 12           // 768 / 64 K-chunks

// ---------------------------------------------------------------------------
// Scratch (device globals; no cudaMalloc allowed)
// ---------------------------------------------------------------------------
__device__ float g_qkv[MROWS * C3];   // (B*T, 3C) qkv projection output
__device__ float g_att[MROWS * CQ];   // (B,T,H,D) attention out, (B*T, C)

__device__ __nv_bfloat16 g_xh[MROWS * CQ], g_xl[MROWS * CQ];
__device__ __nv_bfloat16 g_yh[MROWS * CQ], g_yl[MROWS * CQ];
__device__ __nv_bfloat16 g_wah[C3 * CQ],   g_wal[C3 * CQ];
__device__ __nv_bfloat16 g_wph[CQ * CQ],   g_wpl[CQ * CQ];

// ---------------------------------------------------------------------------
// Portable PTX helpers (all baseline PTX: sm_80-era, legal on compute_103)
// ---------------------------------------------------------------------------
__device__ __forceinline__ uint32_t smem_u32(const void* p) {
    uint32_t a;
    asm("{ .reg .u64 t; cvta.to.shared.u64 t, %1; cvt.u32.u64 %0, t; }"
        : "=r"(a) : "l"(p));
    return a;
}

#define CP_ASYNC16(dst, src) \
    asm volatile("cp.async.cg.shared.global [%0], [%1], 16;" \
                 :: "r"(dst), "l"(src) : "memory")
#define CP_COMMIT() asm volatile("cp.async.commit_group;" ::: "memory")
#define CP_WAIT1()  asm volatile("cp.async.wait_group 1;" ::: "memory")
#define CP_WAIT0()  asm volatile("cp.async.wait_group 0;" ::: "memory")

#define LDSM4(r, addr) \
    asm volatile("ldmatrix.sync.aligned.m8n8.x4.shared.b16 {%0,%1,%2,%3}, [%4];" \
                 : "=r"((r)[0]), "=r"((r)[1]), "=r"((r)[2]), "=r"((r)[3]) \
                 : "r"(addr))

#define MMA16816(d, a, b0, b1) \
    asm volatile("mma.sync.aligned.m16n8k16.row.col.f32.bf16.bf16.f32 " \
                 "{%0,%1,%2,%3}, {%4,%5,%6,%7}, {%8,%9}, {%0,%1,%2,%3};" \
                 : "+f"((d)[0]), "+f"((d)[1]), "+f"((d)[2]), "+f"((d)[3]) \
                 : "r"((a)[0]), "r"((a)[1]), "r"((a)[2]), "r"((a)[3]), \
                   "r"(b0), "r"(b1))

// ---------------------------------------------------------------------------
// Decompose: x -> (hi, lo) bf16 pair, hi = bf16(x), lo = bf16(x - hi)
// ---------------------------------------------------------------------------
__global__ void __launch_bounds__(256)
decompose_kernel(const float4* __restrict__ src,
                 uint2* __restrict__ hi, uint2* __restrict__ lo, int n4)
{
    int i = blockIdx.x * 256 + threadIdx.x;
    if (i >= n4) return;
    float4 v = src[i];
    float f[4] = {v.x, v.y, v.z, v.w};
    union { __nv_bfloat16 h[4]; uint2 u; } H, L;
#pragma unroll
    for (int j = 0; j < 4; j++) {
        H.h[j] = __float2bfloat16(f[j]);
        L.h[j] = __float2bfloat16(f[j] - __bfloat162float(H.h[j]));
    }
    hi[i] = H.u;
    lo[i] = L.u;
}

// ---------------------------------------------------------------------------
// bf16x3 NT GEMM via mma.sync (HMMA):
//   C[m,n] = sum_k A[m,k]*B[n,k] + bias[n],  A=(M,768), B=(N,768) row-major
//   C ~= Ah*Bh + Ah*Bl + Al*Bh (fp32 accumulate)
// CTA tile 128x128, 8 warps (4m x 2n), warp tile 32x64 (2 m16 x 8 n8).
// K-chunks of 64, double-buffered smem via cp.async. SW128 swizzle.
//
// B fragment pairing (bug fixed this round): LDSM4 on a 16-row n-block gives
//   b[0]=(n0-7,k0-7) b[1]=(n8-15,k0-7) b[2]=(n0-7,k8-15) b[3]=(n8-15,k8-15)
// so mma {b0,b1} pairs are {b[0],b[2]} (low n8) and {b[1],b[3]} (high n8).
// ---------------------------------------------------------------------------
#define TILEB 16384
#define STAGEB (4 * TILEB)
#define GEMM_SMEM (2 * STAGEB)   // 131072

__global__ void __launch_bounds__(256, 1)
gemm_bf16x3_mma(const __nv_bfloat16* __restrict__ Ah,
                const __nv_bfloat16* __restrict__ Al,
                const __nv_bfloat16* __restrict__ Bh,
                const __nv_bfloat16* __restrict__ Bl,
                const float* __restrict__ bias,
                float* __restrict__ C, int N)
{
    extern __shared__ char smem[];
    const uint32_t sb = smem_u32(smem);
    const int tid = threadIdx.x;
    const int lane = tid & 31;
    const int w = tid >> 5;
    const int wm = w & 3;        // 0..3 -> 32-row slab
    const int wn = w >> 2;       // 0..1 -> 64-col slab
    const int bm0 = blockIdx.y * 128;
    const int bn0 = blockIdx.x * 128;

    const __nv_bfloat16* src0 = Ah + (long long)bm0 * GK;
    const __nv_bfloat16* src1 = Al + (long long)bm0 * GK;
    const __nv_bfloat16* src2 = Bh + (long long)bn0 * GK;
    const __nv_bfloat16* src3 = Bl + (long long)bn0 * GK;

    // ldmatrix per-thread row mapping (within a 16-row block):
    const int trow = (lane & 7) + ((lane >> 3) & 1) * 8;  // 0..15
    const int tseg = lane >> 4;                           // 0/1: k 16B-seg select

    // Row indices (within the 128-row tile) for this thread's ldmatrix ops
    int rowA[2], rowB[4];
#pragma unroll
    for (int mt = 0; mt < 2; mt++) rowA[mt] = wm * 32 + mt * 16 + trow;
#pragma unroll
    for (int np = 0; np < 4; np++) rowB[np] = wn * 64 + np * 16 + trow;

    float acc[2][8][4];
#pragma unroll
    for (int mt = 0; mt < 2; mt++)
#pragma unroll
        for (int nt = 0; nt < 8; nt++)
#pragma unroll
            for (int j = 0; j < 4; j++) acc[mt][nt][j] = 0.f;

    // --- stage loader: 4 tiles x 128 rows x 8 segs(16B), 16 cp.async/thread
#define STAGE_LOAD(c, buf)                                                    \
    do {                                                                      \
        const uint32_t base_ = sb + (buf) * STAGEB;                           \
        const __nv_bfloat16* sp_[4] = {src0 + (c) * 64, src1 + (c) * 64,      \
                                       src2 + (c) * 64, src3 + (c) * 64};     \
        _Pragma("unroll")                                                     \
        for (int t_ = 0; t_ < 4; t_++) {                                      \
            const uint32_t tb_ = base_ + t_ * TILEB;                          \
            _Pragma("unroll")                                                 \
            for (int it_ = 0; it_ < 4; it_++) {                               \
                int i_ = tid + it_ * 256;                                     \
                int r_ = i_ >> 3, sg_ = i_ & 7;                               \
                uint32_t dst_ = tb_ + r_ * 128 + ((sg_ ^ (r_ & 7)) << 4);     \
                const void* s_ = sp_[t_] + (long long)r_ * GK + sg_ * 8;      \
                CP_ASYNC16(dst_, s_);                                         \
            }                                                                 \
        }                                                                     \
    } while (0)

    STAGE_LOAD(0, 0);
    CP_COMMIT();

    for (int c = 0; c < NCH; c++) {
        const int buf = c & 1;
        if (c + 1 < NCH) {
            STAGE_LOAD(c + 1, buf ^ 1);
            CP_COMMIT();
            CP_WAIT1();
        } else {
            CP_WAIT0();
        }
        __syncthreads();

        const uint32_t tAh = sb + buf * STAGEB;
        const uint32_t tAl = tAh + TILEB;
        const uint32_t tBh = tAh + 2 * TILEB;
        const uint32_t tBl = tAh + 3 * TILEB;

#pragma unroll
        for (int ks = 0; ks < 4; ks++) {
            const int segk = 2 * ks + tseg;
            uint32_t ah[2][4], al[2][4], bh[4][4], bl[4][4];
#pragma unroll
            for (int mt = 0; mt < 2; mt++) {
                uint32_t off = rowA[mt] * 128 + ((segk ^ (rowA[mt] & 7)) << 4);
                LDSM4(ah[mt], tAh + off);
                LDSM4(al[mt], tAl + off);
            }
#pragma unroll
            for (int np = 0; np < 4; np++) {
                uint32_t off = rowB[np] * 128 + ((segk ^ (rowB[np] & 7)) << 4);
                LDSM4(bh[np], tBh + off);
                LDSM4(bl[np], tBl + off);
            }
#pragma unroll
            for (int mt = 0; mt < 2; mt++) {
#pragma unroll
                for (int np = 0; np < 4; np++) {
                    // low n8 of this 16-block: {b[0], b[2]}
                    MMA16816(acc[mt][2 * np],     ah[mt], bh[np][0], bh[np][2]);
                    // high n8: {b[1], b[3]}
                    MMA16816(acc[mt][2 * np + 1], ah[mt], bh[np][1], bh[np][3]);
                    MMA16816(acc[mt][2 * np],     ah[mt], bl[np][0], bl[np][2]);
                    MMA16816(acc[mt][2 * np + 1], ah[mt], bl[np][1], bl[np][3]);
                    MMA16816(acc[mt][2 * np],     al[mt], bh[np][0], bh[np][2]);
                    MMA16816(acc[mt][2 * np + 1], al[mt], bh[np][1], bh[np][3]);
                }
            }
        }
        __syncthreads();
    }

    // Epilogue: D fragment -> global + bias
    const int g = lane >> 2, tg = lane & 3;
#pragma unroll
    for (int mt = 0; mt < 2; mt++) {
        const long long row0 = bm0 + wm * 32 + mt * 16 + g;
#pragma unroll
        for (int nt = 0; nt < 8; nt++) {
            const int col = bn0 + wn * 64 + nt * 8 + tg * 2;
            float2 bi = *(const float2*)&bias[col];
            float2 o0 = make_float2(acc[mt][nt][0] + bi.x, acc[mt][nt][1] + bi.y);
            float2 o1 = make_float2(acc[mt][nt][2] + bi.x, acc[mt][nt][3] + bi.y);
            *(float2*)&C[row0 * N + col]       = o0;
            *(float2*)&C[(row0 + 8) * N + col] = o1;
        }
    }
}

// ---------------------------------------------------------------------------
// Flash attention (causal), fp32 — unchanged (isolating the GEMM change).
// ---------------------------------------------------------------------------
#define ASTR 100
#define ATT_SMEM ((3 * 64 * ASTR + 64 * 64) * sizeof(float))   // 93184 bytes

__global__ void __launch_bounds__(256)
attn_kernel()
{
    extern __shared__ float sm[];
    float* Qs = sm;                 // 64 x 100
    float* Ks = sm + 64 * ASTR;     // 64 x 100
    float* Vs = sm + 2 * 64 * ASTR; // 64 x 100
    float* Ps = sm + 3 * 64 * ASTR; // 64 x 64

    const int tid = threadIdx.x;
    const int lane = tid & 31;
    const int w = tid >> 5;
    const int qt = blockIdx.x;
    const int bh = blockIdx.y;
    const int b = bh >> 3, h = bh & 7;
    const int q0 = qt * 64;

    const float* base = g_qkv + (long long)b * TQ * C3 + h * DQ;

    for (int i = tid; i < 64 * 24; i += 256) {
        int r = i / 24, cg = (i % 24) * 4;
        *(float4*)&Qs[r * ASTR + cg] =
            *(const float4*)&base[(long long)(q0 + r) * C3 + cg];
    }

    float m_i[8], l_i[8], acc[8][3];
#pragma unroll
    for (int qr = 0; qr < 8; qr++) {
        m_i[qr] = -1e30f; l_i[qr] = 0.f;
        acc[qr][0] = acc[qr][1] = acc[qr][2] = 0.f;
    }

    const float scale = 0.1020620726159658f; // 1/sqrt(96)

    for (int j = 0; j <= qt; j++) {
        __syncthreads();
        const int k0r = j * 64;
        for (int i = tid; i < 64 * 24; i += 256) {
            int r = i / 24, cg = (i % 24) * 4;
            long long src = (long long)(k0r + r) * C3 + cg;
            *(float4*)&Ks[r * ASTR + cg] = *(const float4*)&base[src + 768];
            *(float4*)&Vs[r * ASTR + cg] = *(const float4*)&base[src + 1536];
        }
        __syncthreads();

        float s[8][2];
#pragma unroll
        for (int qr = 0; qr < 8; qr++) { s[qr][0] = 0.f; s[qr][1] = 0.f; }

#pragma unroll 6
        for (int c = 0; c < 24; c++) {
            float4 ka = *(const float4*)&Ks[lane * ASTR + c * 4];
            float4 kb = *(const float4*)&Ks[(lane + 32) * ASTR + c * 4];
#pragma unroll
            for (int qr = 0; qr < 8; qr++) {
                float4 qv = *(const float4*)&Qs[(w * 8 + qr) * ASTR + c * 4];
                s[qr][0] += qv.x * ka.x + qv.y * ka.y + qv.z * ka.z + qv.w * ka.w;
                s[qr][1] += qv.x * kb.x + qv.y * kb.y + qv.z * kb.z + qv.w * kb.w;
            }
        }

        const bool diag = (j == qt);
#pragma unroll
        for (int qr = 0; qr < 8; qr++) {
            const int qg = q0 + w * 8 + qr;
            float s0 = s[qr][0] * scale;
            float s1 = s[qr][1] * scale;
            if (diag) {
                if (k0r + lane      > qg) s0 = -1e30f;
                if (k0r + lane + 32 > qg) s1 = -1e30f;
            }
            float mx = fmaxf(s0, s1);
#pragma unroll
            for (int o = 16; o; o >>= 1)
                mx = fmaxf(mx, __shfl_xor_sync(0xffffffffu, mx, o));
            float m_new = fmaxf(m_i[qr], mx);
            float p0 = __expf(s0 - m_new);
            float p1 = __expf(s1 - m_new);
            float rs = p0 + p1;
#pragma unroll
            for (int o = 16; o; o >>= 1)
                rs += __shfl_xor_sync(0xffffffffu, rs, o);
            float alpha = __expf(m_i[qr] - m_new);
            l_i[qr] = l_i[qr] * alpha + rs;
            m_i[qr] = m_new;
            acc[qr][0] *= alpha; acc[qr][1] *= alpha; acc[qr][2] *= alpha;
            Ps[(w * 8 + qr) * 64 + lane]      = p0;
            Ps[(w * 8 + qr) * 64 + lane + 32] = p1;
        }
        __syncwarp();

#pragma unroll 4
        for (int k4 = 0; k4 < 16; k4++) {
            float v[4][3];
#pragma unroll
            for (int u = 0; u < 4; u++) {
                int key = k4 * 4 + u;
                v[u][0] = Vs[key * ASTR + lane];
                v[u][1] = Vs[key * ASTR + lane + 32];
                v[u][2] = Vs[key * ASTR + lane + 64];
            }
#pragma unroll
            for (int qr = 0; qr < 8; qr++) {
                float4 p = *(const float4*)&Ps[(w * 8 + qr) * 64 + k4 * 4];
                acc[qr][0] += p.x * v[0][0] + p.y * v[1][0] + p.z * v[2][0] + p.w * v[3][0];
                acc[qr][1] += p.x * v[0][1] + p.y * v[1][1] + p.z * v[2][1] + p.w * v[3][1];
                acc[qr][2] += p.x * v[0][2] + p.y * v[1][2] + p.z * v[2][2] + p.w * v[3][2];
            }
        }
    }

#pragma unroll
    for (int qr = 0; qr < 8; qr++) {
        float inv = 1.0f / l_i[qr];
        int t = q0 + w * 8 + qr;
        float* o = g_att + ((long long)(b * TQ + t)) * CQ + h * DQ;
        o[lane]      = acc[qr][0] * inv;
        o[lane + 32] = acc[qr][1] * inv;
        o[lane + 64] = acc[qr][2] * inv;
    }
}

// ---------------------------------------------------------------------------
// Launch
// ---------------------------------------------------------------------------
extern "C" void kernel_launch(void* const* d_in, const int* in_sizes, int n_in,
                              void* d_out, int out_size)
{
    const float* x      = (const float*)d_in[0];
    const float* w_attn = (const float*)d_in[1];
    const float* b_attn = (const float*)d_in[2];
    const float* w_proj = (const float*)d_in[3];
    const float* b_proj = (const float*)d_in[4];
    float* out = (float*)d_out;

    float* qkv; cudaGetSymbolAddress((void**)&qkv, g_qkv);
    float* att; cudaGetSymbolAddress((void**)&att, g_att);
    __nv_bfloat16 *xh, *xl, *yh, *yl, *wah, *wal, *wph, *wpl;
    cudaGetSymbolAddress((void**)&xh,  g_xh);
    cudaGetSymbolAddress((void**)&xl,  g_xl);
    cudaGetSymbolAddress((void**)&yh,  g_yh);
    cudaGetSymbolAddress((void**)&yl,  g_yl);
    cudaGetSymbolAddress((void**)&wah, g_wah);
    cudaGetSymbolAddress((void**)&wal, g_wal);
    cudaGetSymbolAddress((void**)&wph, g_wph);
    cudaGetSymbolAddress((void**)&wpl, g_wpl);

    cudaFuncSetAttribute(gemm_bf16x3_mma,
                         cudaFuncAttributeMaxDynamicSharedMemorySize, GEMM_SMEM);
    cudaFuncSetAttribute(attn_kernel,
                         cudaFuncAttributeMaxDynamicSharedMemorySize, (int)ATT_SMEM);

    // 0) hi/lo bf16 decompositions
    {
        int n4 = MROWS * CQ / 4;
        decompose_kernel<<<(n4 + 255) / 256, 256>>>(
            (const float4*)x, (uint2*)xh, (uint2*)xl, n4);
        n4 = C3 * CQ / 4;
        decompose_kernel<<<(n4 + 255) / 256, 256>>>(
            (const float4*)w_attn, (uint2*)wah, (uint2*)wal, n4);
        n4 = CQ * CQ / 4;
        decompose_kernel<<<(n4 + 255) / 256, 256>>>(
            (const float4*)w_proj, (uint2*)wph, (uint2*)wpl, n4);
    }

    // 1) QKV projection via HMMA: (8192 x 768) @ (2304 x 768)^T
    gemm_bf16x3_mma<<<dim3(C3 / 128, MROWS / 128), 256, GEMM_SMEM>>>(
        xh, xl, wah, wal, b_attn, qkv, C3);

    // 2) Causal flash attention (fp32)
    attn_kernel<<<dim3(TQ / 64, BQ * HQ), 256, ATT_SMEM>>>();

    // 3) Decompose attention output, then output projection
    {
        int n4 = MROWS * CQ / 4;
        decompose_kernel<<<(n4 + 255) / 256, 256>>>(
            (const float4*)att, (uint2*)yh, (uint2*)yl, n4);
    }
    gemm_bf16x3_mma<<<dim3(CQ / 128, MROWS / 128), 256, GEMM_SMEM>>>(
        yh, yl, wph, wpl, b_proj, out, CQ);
}

// round 13
// speedup vs baseline: 1.9329x; 1.2219x over previous
#include <cuda_runtime.h>
#include <cuda_bf16.h>
#include <cstdint>

// Problem constants
#define BQ 8
#define TQ 1024
#define CQ 768
#define HQ 8
#define DQ 96
#define C3 2304          // 3*C
#define MROWS (BQ*TQ)    // 8192
#define GK 768           // K dim for both GEMMs
#define NCH 12           // 768 / 64 K-chunks

// ---------------------------------------------------------------------------
// Scratch (device globals; no cudaMalloc allowed)
// ---------------------------------------------------------------------------
__device__ float g_qkv[MROWS * C3];   // (B*T, 3C) qkv projection output
__device__ float g_att[MROWS * CQ];   // (B,T,H,D) attention out, (B*T, C)

__device__ __nv_bfloat16 g_xh[MROWS * CQ], g_xl[MROWS * CQ];
__device__ __nv_bfloat16 g_yh[MROWS * CQ], g_yl[MROWS * CQ];
__device__ __nv_bfloat16 g_wah[C3 * CQ],   g_wal[C3 * CQ];
__device__ __nv_bfloat16 g_wph[CQ * CQ],   g_wpl[CQ * CQ];

// ---------------------------------------------------------------------------
// Portable PTX helpers (all baseline PTX: sm_80-era, legal on compute_103)
// ---------------------------------------------------------------------------
__device__ __forceinline__ uint32_t smem_u32(const void* p) {
    uint32_t a;
    asm("{ .reg .u64 t; cvta.to.shared.u64 t, %1; cvt.u32.u64 %0, t; }"
        : "=r"(a) : "l"(p));
    return a;
}

#define CP_ASYNC16(dst, src) \
    asm volatile("cp.async.cg.shared.global [%0], [%1], 16;" \
                 :: "r"(dst), "l"(src) : "memory")
#define CP_COMMIT() asm volatile("cp.async.commit_group;" ::: "memory")
#define CP_WAIT1()  asm volatile("cp.async.wait_group 1;" ::: "memory")
#define CP_WAIT0()  asm volatile("cp.async.wait_group 0;" ::: "memory")

#define LDSM4(r, addr) \
    asm volatile("ldmatrix.sync.aligned.m8n8.x4.shared.b16 {%0,%1,%2,%3}, [%4];" \
                 : "=r"((r)[0]), "=r"((r)[1]), "=r"((r)[2]), "=r"((r)[3]) \
                 : "r"(addr))

#define MMA16816(d, a, b0, b1) \
    asm volatile("mma.sync.aligned.m16n8k16.row.col.f32.bf16.bf16.f32 " \
                 "{%0,%1,%2,%3}, {%4,%5,%6,%7}, {%8,%9}, {%0,%1,%2,%3};" \
                 : "+f"((d)[0]), "+f"((d)[1]), "+f"((d)[2]), "+f"((d)[3]) \
                 : "r"((a)[0]), "r"((a)[1]), "r"((a)[2]), "r"((a)[3]), \
                   "r"(b0), "r"(b1))

// hi/lo bf16 decomposition of a float4, stored as two 8-byte packs
__device__ __forceinline__ void st_hilo4(void* hdst, void* ldst, float4 v) {
    float f[4] = {v.x, v.y, v.z, v.w};
    union { __nv_bfloat16 b[4]; uint2 u; } H, L;
#pragma unroll
    for (int j = 0; j < 4; j++) {
        H.b[j] = __float2bfloat16(f[j]);
        L.b[j] = __float2bfloat16(f[j] - __bfloat162float(H.b[j]));
    }
    *(uint2*)hdst = H.u;
    *(uint2*)ldst = L.u;
}

// ---------------------------------------------------------------------------
// Decompose: x -> (hi, lo) bf16 pair, hi = bf16(x), lo = bf16(x - hi)
// ---------------------------------------------------------------------------
__global__ void __launch_bounds__(256)
decompose_kernel(const float4* __restrict__ src,
                 uint2* __restrict__ hi, uint2* __restrict__ lo, int n4)
{
    int i = blockIdx.x * 256 + threadIdx.x;
    if (i >= n4) return;
    float4 v = src[i];
    float f[4] = {v.x, v.y, v.z, v.w};
    union { __nv_bfloat16 h[4]; uint2 u; } H, L;
#pragma unroll
    for (int j = 0; j < 4; j++) {
        H.h[j] = __float2bfloat16(f[j]);
        L.h[j] = __float2bfloat16(f[j] - __bfloat162float(H.h[j]));
    }
    hi[i] = H.u;
    lo[i] = L.u;
}

// ---------------------------------------------------------------------------
// bf16x3 NT GEMM via mma.sync (HMMA) — unchanged from R10 (passing).
// ---------------------------------------------------------------------------
#define TILEB 16384
#define STAGEB (4 * TILEB)
#define GEMM_SMEM (2 * STAGEB)   // 131072

__global__ void __launch_bounds__(256, 1)
gemm_bf16x3_mma(const __nv_bfloat16* __restrict__ Ah,
                const __nv_bfloat16* __restrict__ Al,
                const __nv_bfloat16* __restrict__ Bh,
                const __nv_bfloat16* __restrict__ Bl,
                const float* __restrict__ bias,
                float* __restrict__ C, int N)
{
    extern __shared__ char smem[];
    const uint32_t sb = smem_u32(smem);
    const int tid = threadIdx.x;
    const int lane = tid & 31;
    const int w = tid >> 5;
    const int wm = w & 3;        // 0..3 -> 32-row slab
    const int wn = w >> 2;       // 0..1 -> 64-col slab
    const int bm0 = blockIdx.y * 128;
    const int bn0 = blockIdx.x * 128;

    const __nv_bfloat16* src0 = Ah + (long long)bm0 * GK;
    const __nv_bfloat16* src1 = Al + (long long)bm0 * GK;
    const __nv_bfloat16* src2 = Bh + (long long)bn0 * GK;
    const __nv_bfloat16* src3 = Bl + (long long)bn0 * GK;

    const int trow = (lane & 7) + ((lane >> 3) & 1) * 8;  // 0..15
    const int tseg = lane >> 4;                           // 0/1

    int rowA[2], rowB[4];
#pragma unroll
    for (int mt = 0; mt < 2; mt++) rowA[mt] = wm * 32 + mt * 16 + trow;
#pragma unroll
    for (int np = 0; np < 4; np++) rowB[np] = wn * 64 + np * 16 + trow;

    float acc[2][8][4];
#pragma unroll
    for (int mt = 0; mt < 2; mt++)
#pragma unroll
        for (int nt = 0; nt < 8; nt++)
#pragma unroll
            for (int j = 0; j < 4; j++) acc[mt][nt][j] = 0.f;

#define STAGE_LOAD(c, buf)                                                    \
    do {                                                                      \
        const uint32_t base_ = sb + (buf) * STAGEB;                           \
        const __nv_bfloat16* sp_[4] = {src0 + (c) * 64, src1 + (c) * 64,      \
                                       src2 + (c) * 64, src3 + (c) * 64};     \
        _Pragma("unroll")                                                     \
        for (int t_ = 0; t_ < 4; t_++) {                                      \
            const uint32_t tb_ = base_ + t_ * TILEB;                          \
            _Pragma("unroll")                                                 \
            for (int it_ = 0; it_ < 4; it_++) {                               \
                int i_ = tid + it_ * 256;                                     \
                int r_ = i_ >> 3, sg_ = i_ & 7;                               \
                uint32_t dst_ = tb_ + r_ * 128 + ((sg_ ^ (r_ & 7)) << 4);     \
                const void* s_ = sp_[t_] + (long long)r_ * GK + sg_ * 8;      \
                CP_ASYNC16(dst_, s_);                                         \
            }                                                                 \
        }                                                                     \
    } while (0)

    STAGE_LOAD(0, 0);
    CP_COMMIT();

    for (int c = 0; c < NCH; c++) {
        const int buf = c & 1;
        if (c + 1 < NCH) {
            STAGE_LOAD(c + 1, buf ^ 1);
            CP_COMMIT();
            CP_WAIT1();
        } else {
            CP_WAIT0();
        }
        __syncthreads();

        const uint32_t tAh = sb + buf * STAGEB;
        const uint32_t tAl = tAh + TILEB;
        const uint32_t tBh = tAh + 2 * TILEB;
        const uint32_t tBl = tAh + 3 * TILEB;

#pragma unroll
        for (int ks = 0; ks < 4; ks++) {
            const int segk = 2 * ks + tseg;
            uint32_t ah[2][4], al[2][4], bh[4][4], bl[4][4];
#pragma unroll
            for (int mt = 0; mt < 2; mt++) {
                uint32_t off = rowA[mt] * 128 + ((segk ^ (rowA[mt] & 7)) << 4);
                LDSM4(ah[mt], tAh + off);
                LDSM4(al[mt], tAl + off);
            }
#pragma unroll
            for (int np = 0; np < 4; np++) {
                uint32_t off = rowB[np] * 128 + ((segk ^ (rowB[np] & 7)) << 4);
                LDSM4(bh[np], tBh + off);
                LDSM4(bl[np], tBl + off);
            }
#pragma unroll
            for (int mt = 0; mt < 2; mt++) {
#pragma unroll
                for (int np = 0; np < 4; np++) {
                    MMA16816(acc[mt][2 * np],     ah[mt], bh[np][0], bh[np][2]);
                    MMA16816(acc[mt][2 * np + 1], ah[mt], bh[np][1], bh[np][3]);
                    MMA16816(acc[mt][2 * np],     ah[mt], bl[np][0], bl[np][2]);
                    MMA16816(acc[mt][2 * np + 1], ah[mt], bl[np][1], bl[np][3]);
                    MMA16816(acc[mt][2 * np],     al[mt], bh[np][0], bh[np][2]);
                    MMA16816(acc[mt][2 * np + 1], al[mt], bh[np][1], bh[np][3]);
                }
            }
        }
        __syncthreads();
    }

    const int g = lane >> 2, tg = lane & 3;
#pragma unroll
    for (int mt = 0; mt < 2; mt++) {
        const long long row0 = bm0 + wm * 32 + mt * 16 + g;
#pragma unroll
        for (int nt = 0; nt < 8; nt++) {
            const int col = bn0 + wn * 64 + nt * 8 + tg * 2;
            float2 bi = *(const float2*)&bias[col];
            float2 o0 = make_float2(acc[mt][nt][0] + bi.x, acc[mt][nt][1] + bi.y);
            float2 o1 = make_float2(acc[mt][nt][2] + bi.x, acc[mt][nt][3] + bi.y);
            *(float2*)&C[row0 * N + col]       = o0;
            *(float2*)&C[(row0 + 8) * N + col] = o1;
        }
    }
}

// ---------------------------------------------------------------------------
// Flash attention (causal): QK^T via bf16x3 HMMA (warps 0-3), softmax + PV fp32.
// Q/K hi/lo bf16 rows: 96 bf16 = 192 data bytes, stride KSTR=208 bytes.
// In 16B units the stride is 13 == 5 (mod 8), gcd(5,8)=1 -> 8 consecutive rows
// at equal byte offset land in 8 distinct 16B bank-groups: ldmatrix is
// conflict-free with no XOR swizzle. (R12 bug: stride was 112 < 192 -> rows
// overlapped; fixed by arithmetic audit of st_hilo4 bounds.)
// S (64x64 f32) buffer is overwritten in place by P (per-row ownership).
// ---------------------------------------------------------------------------
#define ASTR 100
#define KSTR 208                     // bytes per bf16 tile row (192 data + 16 pad)
#define QTB  (64 * KSTR)             // 13312 bytes per tile
#define OFF_QH 0
#define OFF_QL (1 * QTB)             // 13312
#define OFF_KH (2 * QTB)             // 26624
#define OFF_KL (3 * QTB)             // 39936
#define OFF_V  (4 * QTB)             // 53248: f32, 64 x ASTR = 25600
#define OFF_S  (OFF_V + 64 * ASTR * 4)  // 78848: f32, 64 x 64 = 16384
#define ATT_SMEM (OFF_S + 64 * 64 * 4)  // 95232

__global__ void __launch_bounds__(256)
attn_kernel()
{
    extern __shared__ char smc[];
    const uint32_t sb = smem_u32(smc);
    float* Vs = (float*)(smc + OFF_V);
    float* Ss = (float*)(smc + OFF_S);

    const int tid = threadIdx.x;
    const int lane = tid & 31;
    const int w = tid >> 5;
    const int qt = blockIdx.x;
    const int bh = blockIdx.y;
    const int b = bh >> 3, h = bh & 7;
    const int q0 = qt * 64;

    const float* base = g_qkv + (long long)b * TQ * C3 + h * DQ;
    const float scale = 0.1020620726159658f; // 1/sqrt(96)

    // Load Q tile as hi/lo bf16 (64 rows x 96)
    for (int i = tid; i < 64 * 24; i += 256) {
        int r = i / 24, cg = (i % 24) * 4;
        float4 v = *(const float4*)&base[(long long)(q0 + r) * C3 + cg];
        st_hilo4(smc + OFF_QH + r * KSTR + cg * 2,
                 smc + OFF_QL + r * KSTR + cg * 2, v);
    }

    float m_i[8], l_i[8], acc[8][3];
#pragma unroll
    for (int qr = 0; qr < 8; qr++) {
        m_i[qr] = -1e30f; l_i[qr] = 0.f;
        acc[qr][0] = acc[qr][1] = acc[qr][2] = 0.f;
    }

    for (int j = 0; j <= qt; j++) {
        __syncthreads();
        const int k0r = j * 64;
        // Load K (hi/lo bf16) and V (f32) for this key block
        for (int i = tid; i < 64 * 24; i += 256) {
            int r = i / 24, cg = (i % 24) * 4;
            long long src = (long long)(k0r + r) * C3 + cg;
            float4 kv = *(const float4*)&base[src + 768];
            st_hilo4(smc + OFF_KH + r * KSTR + cg * 2,
                     smc + OFF_KL + r * KSTR + cg * 2, kv);
            *(float4*)&Vs[r * ASTR + cg] = *(const float4*)&base[src + 1536];
        }
        __syncthreads();

        // --- S = Q K^T via bf16x3 HMMA, warps 0-3 (warp w: q rows 16w..16w+15)
        if (w < 4) {
            const int trow = (lane & 7) + ((lane >> 3) & 1) * 8;
            const int tseg = lane >> 4;
            float sacc[8][4];
#pragma unroll
            for (int t = 0; t < 8; t++)
#pragma unroll
                for (int z = 0; z < 4; z++) sacc[t][z] = 0.f;

            const uint32_t abase = sb + OFF_QH + (w * 16 + trow) * KSTR;
#pragma unroll
            for (int kc = 0; kc < 6; kc++) {
                const uint32_t ko = (2 * kc + tseg) * 16;
                uint32_t ah[4], al[4];
                LDSM4(ah, abase + ko);
                LDSM4(al, abase + (OFF_QL - OFF_QH) + ko);
#pragma unroll
                for (int np = 0; np < 4; np++) {
                    const uint32_t bb = sb + OFF_KH + (np * 16 + trow) * KSTR + ko;
                    uint32_t kh4[4], kl4[4];
                    LDSM4(kh4, bb);
                    LDSM4(kl4, bb + (OFF_KL - OFF_KH));
                    MMA16816(sacc[2 * np],     ah, kh4[0], kh4[2]);
                    MMA16816(sacc[2 * np + 1], ah, kh4[1], kh4[3]);
                    MMA16816(sacc[2 * np],     ah, kl4[0], kl4[2]);
                    MMA16816(sacc[2 * np + 1], ah, kl4[1], kl4[3]);
                    MMA16816(sacc[2 * np],     al, kh4[0], kh4[2]);
                    MMA16816(sacc[2 * np + 1], al, kh4[1], kh4[3]);
                }
            }
            // Store scaled S: D fragment (g,tg) -> rows 16w+g, 16w+g+8
            const int g = lane >> 2, tg = lane & 3;
#pragma unroll
            for (int t = 0; t < 8; t++) {
                const int r0 = w * 16 + g, c = t * 8 + tg * 2;
                *(float2*)&Ss[r0 * 64 + c] =
                    make_float2(sacc[t][0] * scale, sacc[t][1] * scale);
                *(float2*)&Ss[(r0 + 8) * 64 + c] =
                    make_float2(sacc[t][2] * scale, sacc[t][3] * scale);
            }
        }
        __syncthreads();

        // --- online softmax per row (warp owns rows 8w..8w+7); P overwrites S
        const bool diag = (j == qt);
#pragma unroll
        for (int qr = 0; qr < 8; qr++) {
            const int row = w * 8 + qr;
            const int qg = q0 + row;
            float s0 = Ss[row * 64 + lane];
            float s1 = Ss[row * 64 + lane + 32];
            if (diag) {
                if (k0r + lane      > qg) s0 = -1e30f;
                if (k0r + lane + 32 > qg) s1 = -1e30f;
            }
            float mx = fmaxf(s0, s1);
#pragma unroll
            for (int o = 16; o; o >>= 1)
                mx = fmaxf(mx, __shfl_xor_sync(0xffffffffu, mx, o));
            float m_new = fmaxf(m_i[qr], mx);
            float p0 = __expf(s0 - m_new);
            float p1 = __expf(s1 - m_new);
            float rs = p0 + p1;
#pragma unroll
            for (int o = 16; o; o >>= 1)
                rs += __shfl_xor_sync(0xffffffffu, rs, o);
            float alpha = __expf(m_i[qr] - m_new);
            l_i[qr] = l_i[qr] * alpha + rs;
            m_i[qr] = m_new;
            acc[qr][0] *= alpha; acc[qr][1] *= alpha; acc[qr][2] *= alpha;
            Ss[row * 64 + lane]      = p0;
            Ss[row * 64 + lane + 32] = p1;
        }
        __syncwarp();

        // --- PV (fp32): lane owns dims (lane, lane+32, lane+64)
#pragma unroll 4
        for (int k4 = 0; k4 < 16; k4++) {
            float v[4][3];
#pragma unroll
            for (int u = 0; u < 4; u++) {
                int key = k4 * 4 + u;
                v[u][0] = Vs[key * ASTR + lane];
                v[u][1] = Vs[key * ASTR + lane + 32];
                v[u][2] = Vs[key * ASTR + lane + 64];
            }
#pragma unroll
            for (int qr = 0; qr < 8; qr++) {
                float4 p = *(const float4*)&Ss[(w * 8 + qr) * 64 + k4 * 4];
                acc[qr][0] += p.x * v[0][0] + p.y * v[1][0] + p.z * v[2][0] + p.w * v[3][0];
                acc[qr][1] += p.x * v[0][1] + p.y * v[1][1] + p.z * v[2][1] + p.w * v[3][1];
                acc[qr][2] += p.x * v[0][2] + p.y * v[1][2] + p.z * v[2][2] + p.w * v[3][2];
            }
        }
    }

    // Normalize + write (B,T,H,D) contiguous
#pragma unroll
    for (int qr = 0; qr < 8; qr++) {
        float inv = 1.0f / l_i[qr];
        int t = q0 + w * 8 + qr;
        float* o = g_att + ((long long)(b * TQ + t)) * CQ + h * DQ;
        o[lane]      = acc[qr][0] * inv;
        o[lane + 32] = acc[qr][1] * inv;
        o[lane + 64] = acc[qr][2] * inv;
    }
}

// ---------------------------------------------------------------------------
// Launch
// ---------------------------------------------------------------------------
extern "C" void kernel_launch(void* const* d_in, const int* in_sizes, int n_in,
                              void* d_out, int out_size)
{
    const float* x      = (const float*)d_in[0];
    const float* w_attn = (const float*)d_in[1];
    const float* b_attn = (const float*)d_in[2];
    const float* w_proj = (const float*)d_in[3];
    const float* b_proj = (const float*)d_in[4];
    float* out = (float*)d_out;

    float* qkv; cudaGetSymbolAddress((void**)&qkv, g_qkv);
    float* att; cudaGetSymbolAddress((void**)&att, g_att);
    __nv_bfloat16 *xh, *xl, *yh, *yl, *wah, *wal, *wph, *wpl;
    cudaGetSymbolAddress((void**)&xh,  g_xh);
    cudaGetSymbolAddress((void**)&xl,  g_xl);
    cudaGetSymbolAddress((void**)&yh,  g_yh);
    cudaGetSymbolAddress((void**)&yl,  g_yl);
    cudaGetSymbolAddress((void**)&wah, g_wah);
    cudaGetSymbolAddress((void**)&wal, g_wal);
    cudaGetSymbolAddress((void**)&wph, g_wph);
    cudaGetSymbolAddress((void**)&wpl, g_wpl);

    cudaFuncSetAttribute(gemm_bf16x3_mma,
                         cudaFuncAttributeMaxDynamicSharedMemorySize, GEMM_SMEM);
    cudaFuncSetAttribute(attn_kernel,
                         cudaFuncAttributeMaxDynamicSharedMemorySize, ATT_SMEM);

    // 0) hi/lo bf16 decompositions
    {
        int n4 = MROWS * CQ / 4;
        decompose_kernel<<<(n4 + 255) / 256, 256>>>(
            (const float4*)x, (uint2*)xh, (uint2*)xl, n4);
        n4 = C3 * CQ / 4;
        decompose_kernel<<<(n4 + 255) / 256, 256>>>(
            (const float4*)w_attn, (uint2*)wah, (uint2*)wal, n4);
        n4 = CQ * CQ / 4;
        decompose_kernel<<<(n4 + 255) / 256, 256>>>(
            (const float4*)w_proj, (uint2*)wph, (uint2*)wpl, n4);
    }

    // 1) QKV projection via HMMA: (8192 x 768) @ (2304 x 768)^T
    gemm_bf16x3_mma<<<dim3(C3 / 128, MROWS / 128), 256, GEMM_SMEM>>>(
        xh, xl, wah, wal, b_attn, qkv, C3);

    // 2) Causal flash attention (HMMA QK^T + fp32 PV)
    attn_kernel<<<dim3(TQ / 64, BQ * HQ), 256, ATT_SMEM>>>();

    // 3) Decompose attention output, then output projection
    {
        int n4 = MROWS * CQ / 4;
        decompose_kernel<<<(n4 + 255) / 256, 256>>>(
            (const float4*)att, (uint2*)yh, (uint2*)yl, n4);
    }
    gemm_bf16x3_mma<<<dim3(CQ / 128, MROWS / 128), 256, GEMM_SMEM>>>(
        yh, yl, wph, wpl, b_proj, out, CQ);
}

// round 14
// speedup vs baseline: 2.3841x; 1.2334x over previous
#include <cuda_runtime.h>
#include <cuda_bf16.h>
#include <cstdint>

// Problem constants
#define BQ 8
#define TQ 1024
#define CQ 768
#define HQ 8
#define DQ 96
#define C3 2304          // 3*C
#define MROWS (BQ*TQ)    // 8192
#define GK 768           // K dim for both GEMMs
#define NCH 12           // 768 / 64 K-chunks

// ---------------------------------------------------------------------------
// Scratch (device globals; no cudaMalloc allowed)
// ---------------------------------------------------------------------------
__device__ __nv_bfloat16 g_qkvh[MROWS * C3], g_qkvl[MROWS * C3]; // qkv hi/lo
__device__ __nv_bfloat16 g_xh[MROWS * CQ], g_xl[MROWS * CQ];
__device__ __nv_bfloat16 g_yh[MROWS * CQ], g_yl[MROWS * CQ];     // attn out hi/lo
__device__ __nv_bfloat16 g_wah[C3 * CQ],   g_wal[C3 * CQ];
__device__ __nv_bfloat16 g_wph[CQ * CQ],   g_wpl[CQ * CQ];

// ---------------------------------------------------------------------------
// Portable PTX helpers (baseline PTX, legal on compute_103)
// ---------------------------------------------------------------------------
__device__ __forceinline__ uint32_t smem_u32(const void* p) {
    uint32_t a;
    asm("{ .reg .u64 t; cvta.to.shared.u64 t, %1; cvt.u32.u64 %0, t; }"
        : "=r"(a) : "l"(p));
    return a;
}

#define CP_ASYNC16(dst, src) \
    asm volatile("cp.async.cg.shared.global [%0], [%1], 16;" \
                 :: "r"(dst), "l"(src) : "memory")
#define CP_COMMIT() asm volatile("cp.async.commit_group;" ::: "memory")
#define CP_WAIT1()  asm volatile("cp.async.wait_group 1;" ::: "memory")
#define CP_WAIT0()  asm volatile("cp.async.wait_group 0;" ::: "memory")

#define LDSM4(r, addr) \
    asm volatile("ldmatrix.sync.aligned.m8n8.x4.shared.b16 {%0,%1,%2,%3}, [%4];" \
                 : "=r"((r)[0]), "=r"((r)[1]), "=r"((r)[2]), "=r"((r)[3]) \
                 : "r"(addr))

#define LDSM4T(r, addr) \
    asm volatile("ldmatrix.sync.aligned.m8n8.x4.trans.shared.b16 {%0,%1,%2,%3}, [%4];" \
                 : "=r"((r)[0]), "=r"((r)[1]), "=r"((r)[2]), "=r"((r)[3]) \
                 : "r"(addr))

#define MMA16816(d, a, b0, b1) \
    asm volatile("mma.sync.aligned.m16n8k16.row.col.f32.bf16.bf16.f32 " \
                 "{%0,%1,%2,%3}, {%4,%5,%6,%7}, {%8,%9}, {%0,%1,%2,%3};" \
                 : "+f"((d)[0]), "+f"((d)[1]), "+f"((d)[2]), "+f"((d)[3]) \
                 : "r"((a)[0]), "r"((a)[1]), "r"((a)[2]), "r"((a)[3]), \
                   "r"(b0), "r"(b1))

// ---------------------------------------------------------------------------
// Decompose: x -> (hi, lo) bf16 pair
// ---------------------------------------------------------------------------
__global__ void __launch_bounds__(256)
decompose_kernel(const float4* __restrict__ src,
                 uint2* __restrict__ hi, uint2* __restrict__ lo, int n4)
{
    int i = blockIdx.x * 256 + threadIdx.x;
    if (i >= n4) return;
    float4 v = src[i];
    float f[4] = {v.x, v.y, v.z, v.w};
    union { __nv_bfloat16 h[4]; uint2 u; } H, L;
#pragma unroll
    for (int j = 0; j < 4; j++) {
        H.h[j] = __float2bfloat16(f[j]);
        L.h[j] = __float2bfloat16(f[j] - __bfloat162float(H.h[j]));
    }
    hi[i] = H.u;
    lo[i] = L.u;
}

// ---------------------------------------------------------------------------
// bf16x3 NT GEMM via mma.sync (HMMA). mode 0: f32 out. mode 1: hi/lo bf16 out.
// ---------------------------------------------------------------------------
#define TILEB 16384
#define STAGEB (4 * TILEB)
#define GEMM_SMEM (2 * STAGEB)   // 131072

__global__ void __launch_bounds__(256, 1)
gemm_bf16x3_mma(const __nv_bfloat16* __restrict__ Ah,
                const __nv_bfloat16* __restrict__ Al,
                const __nv_bfloat16* __restrict__ Bh,
                const __nv_bfloat16* __restrict__ Bl,
                const float* __restrict__ bias,
                float* __restrict__ C,
                __nv_bfloat16* __restrict__ Ch,
                __nv_bfloat16* __restrict__ Cl,
                int N, int mode)
{
    extern __shared__ char smem[];
    const uint32_t sb = smem_u32(smem);
    const int tid = threadIdx.x;
    const int lane = tid & 31;
    const int w = tid >> 5;
    const int wm = w & 3;
    const int wn = w >> 2;
    const int bm0 = blockIdx.y * 128;
    const int bn0 = blockIdx.x * 128;

    const __nv_bfloat16* src0 = Ah + (long long)bm0 * GK;
    const __nv_bfloat16* src1 = Al + (long long)bm0 * GK;
    const __nv_bfloat16* src2 = Bh + (long long)bn0 * GK;
    const __nv_bfloat16* src3 = Bl + (long long)bn0 * GK;

    const int trow = (lane & 7) + ((lane >> 3) & 1) * 8;
    const int tseg = lane >> 4;

    int rowA[2], rowB[4];
#pragma unroll
    for (int mt = 0; mt < 2; mt++) rowA[mt] = wm * 32 + mt * 16 + trow;
#pragma unroll
    for (int np = 0; np < 4; np++) rowB[np] = wn * 64 + np * 16 + trow;

    float acc[2][8][4];
#pragma unroll
    for (int mt = 0; mt < 2; mt++)
#pragma unroll
        for (int nt = 0; nt < 8; nt++)
#pragma unroll
            for (int j = 0; j < 4; j++) acc[mt][nt][j] = 0.f;

#define STAGE_LOAD(c, buf)                                                    \
    do {                                                                      \
        const uint32_t base_ = sb + (buf) * STAGEB;                           \
        const __nv_bfloat16* sp_[4] = {src0 + (c) * 64, src1 + (c) * 64,      \
                                       src2 + (c) * 64, src3 + (c) * 64};     \
        _Pragma("unroll")                                                     \
        for (int t_ = 0; t_ < 4; t_++) {                                      \
            const uint32_t tb_ = base_ + t_ * TILEB;                          \
            _Pragma("unroll")                                                 \
            for (int it_ = 0; it_ < 4; it_++) {                               \
                int i_ = tid + it_ * 256;                                     \
                int r_ = i_ >> 3, sg_ = i_ & 7;                               \
                uint32_t dst_ = tb_ + r_ * 128 + ((sg_ ^ (r_ & 7)) << 4);     \
                const void* s_ = sp_[t_] + (long long)r_ * GK + sg_ * 8;      \
                CP_ASYNC16(dst_, s_);                                         \
            }                                                                 \
        }                                                                     \
    } while (0)

    STAGE_LOAD(0, 0);
    CP_COMMIT();

    for (int c = 0; c < NCH; c++) {
        const int buf = c & 1;
        if (c + 1 < NCH) {
            STAGE_LOAD(c + 1, buf ^ 1);
            CP_COMMIT();
            CP_WAIT1();
        } else {
            CP_WAIT0();
        }
        __syncthreads();

        const uint32_t tAh = sb + buf * STAGEB;
        const uint32_t tAl = tAh + TILEB;
        const uint32_t tBh = tAh + 2 * TILEB;
        const uint32_t tBl = tAh + 3 * TILEB;

#pragma unroll
        for (int ks = 0; ks < 4; ks++) {
            const int segk = 2 * ks + tseg;
            uint32_t ah[2][4], al[2][4], bh[4][4], bl[4][4];
#pragma unroll
            for (int mt = 0; mt < 2; mt++) {
                uint32_t off = rowA[mt] * 128 + ((segk ^ (rowA[mt] & 7)) << 4);
                LDSM4(ah[mt], tAh + off);
                LDSM4(al[mt], tAl + off);
            }
#pragma unroll
            for (int np = 0; np < 4; np++) {
                uint32_t off = rowB[np] * 128 + ((segk ^ (rowB[np] & 7)) << 4);
                LDSM4(bh[np], tBh + off);
                LDSM4(bl[np], tBl + off);
            }
#pragma unroll
            for (int mt = 0; mt < 2; mt++) {
#pragma unroll
                for (int np = 0; np < 4; np++) {
                    MMA16816(acc[mt][2 * np],     ah[mt], bh[np][0], bh[np][2]);
                    MMA16816(acc[mt][2 * np + 1], ah[mt], bh[np][1], bh[np][3]);
                    MMA16816(acc[mt][2 * np],     ah[mt], bl[np][0], bl[np][2]);
                    MMA16816(acc[mt][2 * np + 1], ah[mt], bl[np][1], bl[np][3]);
                    MMA16816(acc[mt][2 * np],     al[mt], bh[np][0], bh[np][2]);
                    MMA16816(acc[mt][2 * np + 1], al[mt], bh[np][1], bh[np][3]);
                }
            }
        }
        __syncthreads();
    }

    const int g = lane >> 2, tg = lane & 3;
#pragma unroll
    for (int mt = 0; mt < 2; mt++) {
        const long long row0 = bm0 + wm * 32 + mt * 16 + g;
#pragma unroll
        for (int nt = 0; nt < 8; nt++) {
            const int col = bn0 + wn * 64 + nt * 8 + tg * 2;
            float2 bi = *(const float2*)&bias[col];
            float o[4] = {acc[mt][nt][0] + bi.x, acc[mt][nt][1] + bi.y,
                          acc[mt][nt][2] + bi.x, acc[mt][nt][3] + bi.y};
            if (mode == 0) {
                *(float2*)&C[row0 * N + col]       = make_float2(o[0], o[1]);
                *(float2*)&C[(row0 + 8) * N + col] = make_float2(o[2], o[3]);
            } else {
                union { __nv_bfloat16 b[2]; uint32_t u; } H0, L0, H1, L1;
#pragma unroll
                for (int z = 0; z < 2; z++) {
                    H0.b[z] = __float2bfloat16(o[z]);
                    L0.b[z] = __float2bfloat16(o[z] - __bfloat162float(H0.b[z]));
                    H1.b[z] = __float2bfloat16(o[z + 2]);
                    L1.b[z] = __float2bfloat16(o[z + 2] - __bfloat162float(H1.b[z]));
                }
                *(uint32_t*)&Ch[row0 * N + col]       = H0.u;
                *(uint32_t*)&Cl[row0 * N + col]       = L0.u;
                *(uint32_t*)&Ch[(row0 + 8) * N + col] = H1.u;
                *(uint32_t*)&Cl[(row0 + 8) * N + col] = L1.u;
            }
        }
    }
}

// ---------------------------------------------------------------------------
// Full-HMMA flash attention (causal).
// QK^T and PV both bf16x3 on all 8 warps. Q/K/V hi/lo bf16 tiles (stride 208B:
// 13 == 5 mod 8, conflict-free ldmatrix). P hi/lo bf16 (stride 144B: 9 == 1 mod
// 8, conflict-free). V as B-operand via ldmatrix.trans: octets (k0,d0),(k0+8,d0),
// (k0,d0+8),(k0+8,d0+8) -> mma pairs {r0,r1},{r2,r3}.
// alpha / 1/l published via smem (softmax row-ownership != fragment rows).
// ---------------------------------------------------------------------------
#define KSTR 208
#define QTB  (64 * KSTR)             // 13312
#define PSTR 144
#define OFF_QH 0
#define OFF_QL (1 * QTB)
#define OFF_KH (2 * QTB)
#define OFF_KL (3 * QTB)
#define OFF_VH (4 * QTB)
#define OFF_VL (5 * QTB)             // 66560
#define OFF_S  (6 * QTB)             // 79872, f32 64x64
#define OFF_PH (OFF_S + 64 * 64 * 4) // 96256
#define OFF_PL (OFF_PH + 64 * PSTR)  // 105472
#define OFF_AL (OFF_PL + 64 * PSTR)  // 114688, 64 f32 (alpha, reused as 1/l)
#define ATT_SMEM (OFF_AL + 256)      // 114944

__global__ void __launch_bounds__(256, 2)
attn_kernel()
{
    extern __shared__ char smc[];
    const uint32_t sb = smem_u32(smc);
    float* Ss = (float*)(smc + OFF_S);
    float* Al = (float*)(smc + OFF_AL);

    const int tid = threadIdx.x;
    const int lane = tid & 31;
    const int w = tid >> 5;
    const int wm = w & 3;            // m16 block for both MMA phases
    const int wn = w >> 2;           // QK: 32-key slab; PV: 48-dim slab
    const int qt = blockIdx.x;
    const int bh = blockIdx.y;
    const int b = bh >> 3, h = bh & 7;
    const int q0 = qt * 64;

    const int trow = (lane & 7) + ((lane >> 3) & 1) * 8;
    const int tseg = lane >> 4;
    const int g = lane >> 2, tg = lane & 3;
    const float scale = 0.1020620726159658f; // 1/sqrt(96)

    const long long hbase = (long long)(b * TQ) * C3 + h * DQ;

    // Load Q tile (hi/lo) via cp.async: 64 rows x 12 segs(16B) per tensor
    for (int i = tid; i < 64 * 12; i += 256) {
        int r = i / 12, sg = i % 12;
        long long src = hbase + (long long)(q0 + r) * C3 + sg * 8;
        CP_ASYNC16(sb + OFF_QH + r * KSTR + sg * 16, g_qkvh + src);
        CP_ASYNC16(sb + OFF_QL + r * KSTR + sg * 16, g_qkvl + src);
    }
    CP_COMMIT();

    float m_i[8], l_i[8];
#pragma unroll
    for (int qr = 0; qr < 8; qr++) { m_i[qr] = -1e30f; l_i[qr] = 0.f; }

    float pacc[6][4];
#pragma unroll
    for (int t = 0; t < 6; t++)
#pragma unroll
        for (int z = 0; z < 4; z++) pacc[t][z] = 0.f;

    // Per-lane V trans-ldmatrix base (octet m: row += (m&1)*8, col += (m>>1)*8)
    const uint32_t vtb = sb + OFF_VH
        + (((lane >> 3) & 1) * 8 + (lane & 7)) * KSTR
        + (lane >> 4) * 16 + wn * 48 * 2;

    for (int j = 0; j <= qt; j++) {
        __syncthreads();   // prev iter's smem reads done before overwrite
        const int k0r = j * 64;
        for (int i = tid; i < 64 * 12; i += 256) {
            int r = i / 12, sg = i % 12;
            long long srck = hbase + (long long)(k0r + r) * C3 + 768 + sg * 8;
            long long srcv = srck + 768;
            CP_ASYNC16(sb + OFF_KH + r * KSTR + sg * 16, g_qkvh + srck);
            CP_ASYNC16(sb + OFF_KL + r * KSTR + sg * 16, g_qkvl + srck);
            CP_ASYNC16(sb + OFF_VH + r * KSTR + sg * 16, g_qkvh + srcv);
            CP_ASYNC16(sb + OFF_VL + r * KSTR + sg * 16, g_qkvl + srcv);
        }
        CP_COMMIT();
        CP_WAIT0();
        __syncthreads();

        // --- QK^T: warp (wm, wn) -> S rows 16wm..+15, keys 32wn..+31
        {
            float sacc[4][4];
#pragma unroll
            for (int t = 0; t < 4; t++)
#pragma unroll
                for (int z = 0; z < 4; z++) sacc[t][z] = 0.f;

            const uint32_t abase = sb + OFF_QH + (wm * 16 + trow) * KSTR;
#pragma unroll
            for (int kc = 0; kc < 6; kc++) {
                const uint32_t ko = (2 * kc + tseg) * 16;
                uint32_t qh4[4], ql4[4];
                LDSM4(qh4, abase + ko);
                LDSM4(ql4, abase + QTB + ko);
#pragma unroll
                for (int nb = 0; nb < 2; nb++) {
                    const uint32_t bb = sb + OFF_KH
                        + (wn * 32 + nb * 16 + trow) * KSTR + ko;
                    uint32_t kh4[4], kl4[4];
                    LDSM4(kh4, bb);
                    LDSM4(kl4, bb + QTB);
                    MMA16816(sacc[2 * nb],     qh4, kh4[0], kh4[2]);
                    MMA16816(sacc[2 * nb + 1], qh4, kh4[1], kh4[3]);
                    MMA16816(sacc[2 * nb],     qh4, kl4[0], kl4[2]);
                    MMA16816(sacc[2 * nb + 1], qh4, kl4[1], kl4[3]);
                    MMA16816(sacc[2 * nb],     ql4, kh4[0], kh4[2]);
                    MMA16816(sacc[2 * nb + 1], ql4, kh4[1], kh4[3]);
                }
            }
#pragma unroll
            for (int t = 0; t < 4; t++) {
                const int r0 = wm * 16 + g, c = wn * 32 + t * 8 + tg * 2;
                *(float2*)&Ss[r0 * 64 + c] =
                    make_float2(sacc[t][0] * scale, sacc[t][1] * scale);
                *(float2*)&Ss[(r0 + 8) * 64 + c] =
                    make_float2(sacc[t][2] * scale, sacc[t][3] * scale);
            }
        }
        __syncthreads();

        // --- online softmax: warp w owns rows 8w..8w+7; writes P hi/lo + alpha
        const bool diag = (j == qt);
#pragma unroll
        for (int qr = 0; qr < 8; qr++) {
            const int row = w * 8 + qr;
            const int qg = q0 + row;
            float s0 = Ss[row * 64 + lane];
            float s1 = Ss[row * 64 + lane + 32];
            if (diag) {
                if (k0r + lane      > qg) s0 = -1e30f;
                if (k0r + lane + 32 > qg) s1 = -1e30f;
            }
            float mx = fmaxf(s0, s1);
#pragma unroll
            for (int o = 16; o; o >>= 1)
                mx = fmaxf(mx, __shfl_xor_sync(0xffffffffu, mx, o));
            float m_new = fmaxf(m_i[qr], mx);
            float p0 = __expf(s0 - m_new);
            float p1 = __expf(s1 - m_new);
            float rs = p0 + p1;
#pragma unroll
            for (int o = 16; o; o >>= 1)
                rs += __shfl_xor_sync(0xffffffffu, rs, o);
            float alpha = __expf(m_i[qr] - m_new);
            l_i[qr] = l_i[qr] * alpha + rs;
            m_i[qr] = m_new;
            __nv_bfloat16 h0 = __float2bfloat16(p0);
            __nv_bfloat16 h1 = __float2bfloat16(p1);
            *(__nv_bfloat16*)(smc + OFF_PH + row * PSTR + lane * 2)        = h0;
            *(__nv_bfloat16*)(smc + OFF_PH + row * PSTR + (lane + 32) * 2) = h1;
            *(__nv_bfloat16*)(smc + OFF_PL + row * PSTR + lane * 2) =
                __float2bfloat16(p0 - __bfloat162float(h0));
            *(__nv_bfloat16*)(smc + OFF_PL + row * PSTR + (lane + 32) * 2) =
                __float2bfloat16(p1 - __bfloat162float(h1));
            if (lane == 0) Al[row] = alpha;
        }
        __syncthreads();

        // --- PV: rescale fragments by alpha, then bf16x3 HMMA accumulate
        {
            const float a0 = Al[wm * 16 + g];
            const float a1 = Al[wm * 16 + g + 8];
#pragma unroll
            for (int t = 0; t < 6; t++) {
                pacc[t][0] *= a0; pacc[t][1] *= a0;
                pacc[t][2] *= a1; pacc[t][3] *= a1;
            }
            const uint32_t pbase = sb + OFF_PH + (wm * 16 + trow) * PSTR;
#pragma unroll
            for (int kc = 0; kc < 4; kc++) {
                const uint32_t ko = (2 * kc + tseg) * 16;
                uint32_t ph4[4], pl4[4];
                LDSM4(ph4, pbase + ko);
                LDSM4(pl4, pbase + 64 * PSTR + ko);
#pragma unroll
                for (int nb = 0; nb < 3; nb++) {
                    const uint32_t vb = vtb + kc * 16 * KSTR + nb * 32;
                    uint32_t vh4[4], vl4[4];
                    LDSM4T(vh4, vb);
                    LDSM4T(vl4, vb + QTB);
                    MMA16816(pacc[2 * nb],     ph4, vh4[0], vh4[1]);
                    MMA16816(pacc[2 * nb + 1], ph4, vh4[2], vh4[3]);
                    MMA16816(pacc[2 * nb],     ph4, vl4[0], vl4[1]);
                    MMA16816(pacc[2 * nb + 1], ph4, vl4[2], vl4[3]);
                    MMA16816(pacc[2 * nb],     pl4, vh4[0], vh4[1]);
                    MMA16816(pacc[2 * nb + 1], pl4, vh4[2], vh4[3]);
                }
            }
        }
    }

    // Publish 1/l (reuse Al buffer; all alpha consumers are done)
    __syncthreads();
#pragma unroll
    for (int qr = 0; qr < 8; qr++)
        if (lane == 0) Al[w * 8 + qr] = 1.0f / l_i[qr];
    __syncthreads();

    // Epilogue: normalize, hi/lo decompose, write y (B*T, C) at col h*96+dim
    {
        const float n0 = Al[wm * 16 + g];
        const float n1 = Al[wm * 16 + g + 8];
        const long long r0 = (long long)(b * TQ + q0 + wm * 16 + g);
#pragma unroll
        for (int t = 0; t < 6; t++) {
            const int c = wn * 48 + t * 8 + tg * 2;
            float o[4] = {pacc[t][0] * n0, pacc[t][1] * n0,
                          pacc[t][2] * n1, pacc[t][3] * n1};
            union { __nv_bfloat16 b2[2]; uint32_t u; } H0, L0, H1, L1;
#pragma unroll
            for (int z = 0; z < 2; z++) {
                H0.b2[z] = __float2bfloat16(o[z]);
                L0.b2[z] = __float2bfloat16(o[z] - __bfloat162float(H0.b2[z]));
                H1.b2[z] = __float2bfloat16(o[z + 2]);
                L1.b2[z] = __float2bfloat16(o[z + 2] - __bfloat162float(H1.b2[z]));
            }
            *(uint32_t*)&g_yh[r0 * CQ + h * DQ + c]       = H0.u;
            *(uint32_t*)&g_yl[r0 * CQ + h * DQ + c]       = L0.u;
            *(uint32_t*)&g_yh[(r0 + 8) * CQ + h * DQ + c] = H1.u;
            *(uint32_t*)&g_yl[(r0 + 8) * CQ + h * DQ + c] = L1.u;
        }
    }
}

// ---------------------------------------------------------------------------
// Launch
// ---------------------------------------------------------------------------
extern "C" void kernel_launch(void* const* d_in, const int* in_sizes, int n_in,
                              void* d_out, int out_size)
{
    const float* x      = (const float*)d_in[0];
    const float* w_attn = (const float*)d_in[1];
    const float* b_attn = (const float*)d_in[2];
    const float* w_proj = (const float*)d_in[3];
    const float* b_proj = (const float*)d_in[4];
    float* out = (float*)d_out;

    __nv_bfloat16 *qkvh, *qkvl, *xh, *xl, *yh, *yl, *wah, *wal, *wph, *wpl;
    cudaGetSymbolAddress((void**)&qkvh, g_qkvh);
    cudaGetSymbolAddress((void**)&qkvl, g_qkvl);
    cudaGetSymbolAddress((void**)&xh,  g_xh);
    cudaGetSymbolAddress((void**)&xl,  g_xl);
    cudaGetSymbolAddress((void**)&yh,  g_yh);
    cudaGetSymbolAddress((void**)&yl,  g_yl);
    cudaGetSymbolAddress((void**)&wah, g_wah);
    cudaGetSymbolAddress((void**)&wal, g_wal);
    cudaGetSymbolAddress((void**)&wph, g_wph);
    cudaGetSymbolAddress((void**)&wpl, g_wpl);

    cudaFuncSetAttribute(gemm_bf16x3_mma,
                         cudaFuncAttributeMaxDynamicSharedMemorySize, GEMM_SMEM);
    cudaFuncSetAttribute(attn_kernel,
                         cudaFuncAttributeMaxDynamicSharedMemorySize, ATT_SMEM);

    // 0) hi/lo bf16 decompositions of inputs/weights
    {
        int n4 = MROWS * CQ / 4;
        decompose_kernel<<<(n4 + 255) / 256, 256>>>(
            (const float4*)x, (uint2*)xh, (uint2*)xl, n4);
        n4 = C3 * CQ / 4;
        decompose_kernel<<<(n4 + 255) / 256, 256>>>(
            (const float4*)w_attn, (uint2*)wah, (uint2*)wal, n4);
        n4 = CQ * CQ / 4;
        decompose_kernel<<<(n4 + 255) / 256, 256>>>(
            (const float4*)w_proj, (uint2*)wph, (uint2*)wpl, n4);
    }

    // 1) QKV projection -> hi/lo bf16 qkv directly (mode 1)
    gemm_bf16x3_mma<<<dim3(C3 / 128, MROWS / 128), 256, GEMM_SMEM>>>(
        xh, xl, wah, wal, b_attn, nullptr, qkvh, qkvl, C3, 1);

    // 2) Full-HMMA causal flash attention -> hi/lo bf16 y directly
    attn_kernel<<<dim3(TQ / 64, BQ * HQ), 256, ATT_SMEM>>>();

    // 3) Output projection -> f32 out (mode 0)
    gemm_bf16x3_mma<<<dim3(CQ / 128, MROWS / 128), 256, GEMM_SMEM>>>(
        yh, yl, wph, wpl, b_proj, out, nullptr, nullptr, CQ, 0);
}